// round 11
// baseline (speedup 1.0000x reference)
#include <cuda_runtime.h>
#include <cuda_bf16.h>
#include <cstdint>

#define NN   50000
#define EE   800000
#define TT   4
#define HH   8
#define C1V  16
#define C2V  8
#define DD   128
#define HC1  128          // H*C1
#define HC2  64           // H*C2
#define OUTW 256          // T*H*C2
#define LRELU 0.2f

#define NSEG (NN * TT)    // 200000 (type,node) segments
#define NB2  196          // ceil(NSEG/1024)

// ---------------- scratch (static device globals; no allocation) -------------
__device__ __align__(16) float g_h1 [TT * NN * HC1];       // GEMM1 out (all t)
__device__ __align__(16) float g_h2 [TT * NN * HC2];       // GEMM2 out (all t)
__device__ __align__(16) float g_ss [TT * NN * HH];
__device__ __align__(16) float g_sd [TT * NN * HH];
__device__ __align__(16) __nv_bfloat16 g_xh [NN * DD];
__device__ __align__(16) __nv_bfloat16 g_xl [NN * DD];
__device__ __align__(16) __nv_bfloat16 g_h1gh[TT * NN * HC1];
__device__ __align__(16) __nv_bfloat16 g_h1gl[TT * NN * HC1];
__device__ __align__(16) __nv_bfloat16 gW1h[TT * HC1 * DD];
__device__ __align__(16) __nv_bfloat16 gW1l[TT * HC1 * DD];
__device__ __align__(16) __nv_bfloat16 gW2h[TT * HC2 * HC1];
__device__ __align__(16) __nv_bfloat16 gW2l[TT * HC2 * HC1];
__device__ int g_cnt [NSEG];
__device__ int g_offs[NSEG];
__device__ int g_cur [NSEG];
__device__ int g_src [EE];     // source node ids, sorted by (type,dst)
__device__ int g_aux [256];

// ============================ helpers ========================================
__device__ __forceinline__ uint32_t smem_u32(const void* p) {
    uint32_t a;
    asm("{ .reg .u64 t; cvta.to.shared.u64 t, %1; cvt.u32.u64 %0, t; }"
        : "=r"(a) : "l"(p));
    return a;
}

#define LDMX4(r0, r1, r2, r3, addr) \
    asm volatile("ldmatrix.sync.aligned.m8n8.x4.shared.b16 {%0,%1,%2,%3}, [%4];" \
        : "=r"(r0), "=r"(r1), "=r"(r2), "=r"(r3) : "r"(addr))

__device__ __forceinline__ void mma_bf16(float& c0, float& c1, float& c2, float& c3,
                                         uint32_t a0, uint32_t a1, uint32_t a2, uint32_t a3,
                                         uint32_t b0, uint32_t b1) {
    asm volatile(
        "mma.sync.aligned.m16n8k16.row.col.f32.bf16.bf16.f32 "
        "{%0,%1,%2,%3}, {%4,%5,%6,%7}, {%8,%9}, {%0,%1,%2,%3};"
        : "+f"(c0), "+f"(c1), "+f"(c2), "+f"(c3)
        : "r"(a0), "r"(a1), "r"(a2), "r"(a3), "r"(b0), "r"(b1));
}

// ---------------- (type,dst) CSR construction --------------------------------
__global__ void k_count(const int* __restrict__ dst, const int* __restrict__ ety) {
    int e = blockIdx.x * blockDim.x + threadIdx.x;
    if (e < EE) atomicAdd(&g_cnt[ety[e] * NN + dst[e]], 1);
}

__global__ void k_scan_block() {
    __shared__ int sh[1024];
    int i = blockIdx.x * 1024 + threadIdx.x;
    int v = (i < NSEG) ? g_cnt[i] : 0;
    sh[threadIdx.x] = v;
    __syncthreads();
    for (int d = 1; d < 1024; d <<= 1) {
        int t = (threadIdx.x >= d) ? sh[threadIdx.x - d] : 0;
        __syncthreads();
        sh[threadIdx.x] += t;
        __syncthreads();
    }
    if (i < NSEG) g_offs[i] = sh[threadIdx.x] - v;   // exclusive
    if (threadIdx.x == 1023) g_aux[blockIdx.x] = sh[1023];
}

__global__ void k_scan_aux() {
    __shared__ int sh[256];
    int tid = threadIdx.x;
    int v = (tid < NB2) ? g_aux[tid] : 0;
    sh[tid] = v;
    __syncthreads();
    for (int d = 1; d < 256; d <<= 1) {
        int t = (tid >= d) ? sh[tid - d] : 0;
        __syncthreads();
        sh[tid] += t;
        __syncthreads();
    }
    if (tid < NB2) g_aux[tid] = sh[tid] - v;         // exclusive
}

__global__ void k_add_aux() {
    int i = blockIdx.x * 1024 + threadIdx.x;
    if (i < NSEG) {
        int v = g_offs[i] + g_aux[blockIdx.x];
        g_offs[i] = v;
        g_cur[i]  = v;
    }
}

__global__ void k_scatter(const int* __restrict__ srcl, const int* __restrict__ dst,
                          const int* __restrict__ ety) {
    int e = blockIdx.x * blockDim.x + threadIdx.x;
    if (e < EE) {
        int pos = atomicAdd(&g_cur[ety[e] * NN + dst[e]], 1);
        g_src[pos] = srcl[e];
    }
}

// ---------------- combined prep: x split + weight transpose/split -------------
__global__ void k_prep(const float* __restrict__ x,
                       const float* __restrict__ W1, const float* __restrict__ W2) {
    const int NX = NN * DD;          // 6,400,000
    const int N1 = TT * HC1 * DD;    // 65536
    const int N2 = TT * HC2 * HC1;   // 32768
    int i = blockIdx.x * blockDim.x + threadIdx.x;
    if (i < NX) {
        float v = x[i];
        __nv_bfloat16 h = __float2bfloat16(v);
        g_xh[i] = h;
        g_xl[i] = __float2bfloat16(v - __bfloat162float(h));
    } else if (i < NX + N1) {
        int j = i - NX;
        int t = j >> 14, r = j & 16383;
        int n = r >> 7, k = r & 127;
        float v = W1[(t << 14) + k * HC1 + n];
        __nv_bfloat16 h = __float2bfloat16(v);
        gW1h[j] = h;
        gW1l[j] = __float2bfloat16(v - __bfloat162float(h));
    } else if (i < NX + N1 + N2) {
        int j = i - NX - N1;
        int t = j >> 13, r = j & 8191;
        int n = r >> 7, k = r & 127;
        float v = W2[t * 8192 + k * HC2 + n];
        __nv_bfloat16 h = __float2bfloat16(v);
        gW2h[j] = h;
        gW2l[j] = __float2bfloat16(v - __bfloat162float(h));
    }
}

// ---------------- HMMA bf16-split GEMM (batched over t via grid.y) -----------
// MT x NT tile, 256 threads (8 warps: 2 x 4), 3-term bf16 split, fp32 acc.
template <int NT, int MT>
__global__ void __launch_bounds__(256, 2)
k_gemm_mma(const __nv_bfloat16* __restrict__ Ah, const __nv_bfloat16* __restrict__ Al,
           size_t aTstride,
           const __nv_bfloat16* __restrict__ Bh, const __nv_bfloat16* __restrict__ Bl,
           float* __restrict__ C, int M) {
    constexpr int K    = 128;
    constexpr int STRB = 272;
    constexpr int ASZ  = MT * STRB;
    constexpr int BSZ  = NT * STRB;
    constexpr int NW   = NT / 4;              // cols per warp
    constexpr int NF   = NW / 8;              // n8 frags per warp
    constexpr int MF   = MT / 32;             // m16 frags per warp

    extern __shared__ __align__(16) char smem[];
    uint32_t sb = smem_u32(smem);
    const uint32_t As = sb;
    const uint32_t Bs = sb + 2 * ASZ;

    int tid = threadIdx.x, wid = tid >> 5, lane = tid & 31;
    int m0 = blockIdx.x * MT;
    int t = blockIdx.y;
    Ah += (size_t)t * aTstride;
    Al += (size_t)t * aTstride;
    Bh += (size_t)t * NT * K;
    Bl += (size_t)t * NT * K;
    C  += (size_t)t * NN * NT;

    {
        for (int idx = tid; idx < MT * 16; idx += 256) {
            int row = idx >> 4, c = idx & 15;
            int gm = m0 + row;
            uint4 vh = make_uint4(0, 0, 0, 0), vl = vh;
            if (gm < M) {
                vh = *(const uint4*)&Ah[(size_t)gm * K + c * 8];
                vl = *(const uint4*)&Al[(size_t)gm * K + c * 8];
            }
            char* ph = smem + row * STRB + c * 16;
            *(uint4*)ph = vh;
            *(uint4*)(ph + ASZ) = vl;
        }
        for (int idx = tid; idx < NT * 16; idx += 256) {
            int row = idx >> 4, c = idx & 15;
            uint4 vh = *(const uint4*)&Bh[(size_t)row * K + c * 8];
            uint4 vl = *(const uint4*)&Bl[(size_t)row * K + c * 8];
            char* ph = smem + 2 * ASZ + row * STRB + c * 16;
            *(uint4*)ph = vh;
            *(uint4*)(ph + BSZ) = vl;
        }
    }
    __syncthreads();

    int warpM = wid >> 2;        // 0..1
    int warpN = wid & 3;         // 0..3
    int lr = lane & 7, lg = lane >> 3;

    uint32_t aRow = warpM * (MT / 2) + lr + (lg & 1) * 8;
    uint32_t aCol = (lg >> 1) * 8;
    uint32_t bRow = warpN * NW + lr + (lg >> 1) * 8;
    uint32_t bCol = (lg & 1) * 8;

    float c[MF][NF][4];
#pragma unroll
    for (int mf = 0; mf < MF; mf++)
#pragma unroll
        for (int nf = 0; nf < NF; nf++)
#pragma unroll
            for (int j = 0; j < 4; j++) c[mf][nf][j] = 0.f;

#pragma unroll
    for (int p = 0; p < 3; p++) {
        uint32_t Abase = As + ((p == 2) ? ASZ : 0);
        uint32_t Bbase = Bs + ((p == 1) ? BSZ : 0);
#pragma unroll
        for (int ks = 0; ks < 8; ks++) {
            int k0 = ks * 16;
            uint32_t a[MF][4];
#pragma unroll
            for (int mf = 0; mf < MF; mf++) {
                uint32_t ad = Abase + (aRow + mf * 16) * STRB + (k0 + aCol) * 2;
                LDMX4(a[mf][0], a[mf][1], a[mf][2], a[mf][3], ad);
            }
            uint32_t b[NF][2];
#pragma unroll
            for (int nf2 = 0; nf2 < NF / 2; nf2++) {
                uint32_t bd = Bbase + (bRow + nf2 * 16) * STRB + (k0 + bCol) * 2;
                uint32_t r0, r1, r2, r3;
                LDMX4(r0, r1, r2, r3, bd);
                b[2 * nf2][0] = r0; b[2 * nf2][1] = r1;
                b[2 * nf2 + 1][0] = r2; b[2 * nf2 + 1][1] = r3;
            }
#pragma unroll
            for (int mf = 0; mf < MF; mf++)
#pragma unroll
                for (int nf = 0; nf < NF; nf++)
                    mma_bf16(c[mf][nf][0], c[mf][nf][1], c[mf][nf][2], c[mf][nf][3],
                             a[mf][0], a[mf][1], a[mf][2], a[mf][3],
                             b[nf][0], b[nf][1]);
        }
    }

    int g = lane >> 2, tq = lane & 3;
#pragma unroll
    for (int mf = 0; mf < MF; mf++) {
        int m = m0 + warpM * (MT / 2) + mf * 16 + g;
#pragma unroll
        for (int nf = 0; nf < NF; nf++) {
            int n = warpN * NW + nf * 8 + tq * 2;
            if (m < M)
                *(float2*)&C[(size_t)m * NT + n] = make_float2(c[mf][nf][0], c[mf][nf][1]);
            if (m + 8 < M)
                *(float2*)&C[(size_t)(m + 8) * NT + n] = make_float2(c[mf][nf][2], c[mf][nf][3]);
        }
    }
}

// ---------------- attention score precompute (batched over t) ----------------
template <int C>
__global__ void k_scores(const float* __restrict__ feat,
                         const float* __restrict__ a_s, const float* __restrict__ a_d) {
    int idx = blockIdx.x * blockDim.x + threadIdx.x;
    if (idx >= TT * NN * HH) return;
    int tn = idx >> 3, hd = idx & 7;
    int t = tn / NN;
    const float* f = &feat[(size_t)tn * 8 * C + hd * C];
    const float* as = &a_s[(t * HH + hd) * C];
    const float* ad = &a_d[(t * HH + hd) * C];
    float s1 = 0.f, s2 = 0.f;
#pragma unroll
    for (int c4 = 0; c4 < C / 4; c4++) {
        float4 v = *(const float4*)&f[c4 * 4];
        float4 w1 = *(const float4*)&as[c4 * 4];
        float4 w2 = *(const float4*)&ad[c4 * 4];
        s1 += v.x * w1.x + v.y * w1.y + v.z * w1.z + v.w * w1.w;
        s2 += v.x * w2.x + v.y * w2.y + v.z * w2.z + v.w * w2.w;
    }
    g_ss[idx] = s1;
    g_sd[idx] = s2;
}

// ---------------- GAT: one warp per (type,node), online softmax, MLP=4 -------
template <int C, bool BF16OUT>
__global__ void k_gat(const float* __restrict__ featbase,
                      const float* __restrict__ biasbase,
                      float* __restrict__ outbase, int ostride, int ocol_step,
                      __nv_bfloat16* __restrict__ outh,
                      __nv_bfloat16* __restrict__ outl, int dorelu) {
    constexpr int HC = 8 * C;
    constexpr int VW = C / 4;               // 4 for C=16, 2 for C=8
    int seg = (blockIdx.x * blockDim.x + threadIdx.x) >> 5;
    if (seg >= NSEG) return;
    int lane = threadIdx.x & 31;
    int t = seg / NN;
    int node = seg - t * NN;
    int start = g_offs[seg];
    int deg   = g_cnt[seg];

    const float* feat = featbase + (size_t)t * NN * HC;
    const float* ssp  = g_ss + (size_t)t * NN * 8;
    const float* sdp  = g_sd + (size_t)t * NN * 8;
    const float* bias = biasbase + t * HC;

    int hd = lane >> 2;
    int cbase = (lane & 3) * VW;
    float sd_h = sdp[node * 8 + hd];

    // self-loop seeds the online softmax state
    float m = ssp[node * 8 + hd] + sd_h;
    m = m > 0.f ? m : LRELU * m;
    float denom = 1.f;

    float acc[VW];
    {
        const float* fp = &feat[(size_t)node * HC + hd * C + cbase];
        if constexpr (VW == 4) {
            float4 hv = *(const float4*)fp;
            acc[0] = hv.x; acc[1] = hv.y; acc[2] = hv.z; acc[3] = hv.w;
        } else {
            float2 hv = *(const float2*)fp;
            acc[0] = hv.x; acc[1] = hv.y;
        }
    }

#pragma unroll 1
    for (int i0 = 0; i0 < deg; i0 += 4) {
        int cnt = deg - i0; if (cnt > 4) cnt = 4;
        int s4[4];
        float u4[4];
        float fv[4][VW];
#pragma unroll
        for (int j = 0; j < 4; j++)
            if (j < cnt) s4[j] = g_src[start + i0 + j];
#pragma unroll
        for (int j = 0; j < 4; j++)
            if (j < cnt) u4[j] = ssp[s4[j] * 8 + hd] + sd_h;
#pragma unroll
        for (int j = 0; j < 4; j++) {
            if (j < cnt) {
                const float* fp = &feat[(size_t)s4[j] * HC + hd * C + cbase];
                if constexpr (VW == 4) {
                    float4 hv = *(const float4*)fp;
                    fv[j][0] = hv.x; fv[j][1] = hv.y; fv[j][2] = hv.z; fv[j][3] = hv.w;
                } else {
                    float2 hv = *(const float2*)fp;
                    fv[j][0] = hv.x; fv[j][1] = hv.y;
                }
            }
        }
#pragma unroll
        for (int j = 0; j < 4; j++) {
            if (j < cnt) {
                float u = u4[j];
                u = u > 0.f ? u : LRELU * u;
                float mn = fmaxf(m, u);
                float r  = __expf(m - mn);
                float pe = __expf(u - mn);
                denom = denom * r + pe;
#pragma unroll
                for (int v = 0; v < VW; v++) acc[v] = acc[v] * r + pe * fv[j][v];
                m = mn;
            }
        }
    }

    float inv = 1.f / denom;
    float o[VW];
#pragma unroll
    for (int j = 0; j < VW; j++) {
        float v = acc[j] * inv + bias[hd * C + cbase + j];
        if (dorelu) v = fmaxf(v, 0.f);
        o[j] = v;
    }
    if constexpr (BF16OUT) {
        size_t ob = ((size_t)t * NN + node) * HC + hd * C + cbase;
#pragma unroll
        for (int j = 0; j < VW; j += 2) {
            __nv_bfloat16 h0 = __float2bfloat16(o[j]);
            __nv_bfloat16 h1b = __float2bfloat16(o[j + 1]);
            __nv_bfloat162 hp; hp.x = h0; hp.y = h1b;
            __nv_bfloat162 lp;
            lp.x = __float2bfloat16(o[j] - __bfloat162float(h0));
            lp.y = __float2bfloat16(o[j + 1] - __bfloat162float(h1b));
            *(__nv_bfloat162*)&outh[ob + j] = hp;
            *(__nv_bfloat162*)&outl[ob + j] = lp;
        }
    } else {
        float* op = &outbase[(size_t)node * ostride + t * ocol_step + hd * C + cbase];
        if constexpr (VW == 4) {
            *(float4*)op = make_float4(o[0], o[1], o[2], o[3]);
        } else {
            *(float2*)op = make_float2(o[0], o[1]);
        }
    }
}

// ---------------- launch ------------------------------------------------------
extern "C" void kernel_launch(void* const* d_in, const int* in_sizes, int n_in,
                              void* d_out, int out_size) {
    const float* x     = (const float*)d_in[0];
    const int*   esrc  = (const int*)  d_in[1];
    const int*   edst  = (const int*)  d_in[2];
    const int*   etype = (const int*)  d_in[3];
    const float* W1    = (const float*)d_in[4];
    const float* a1s   = (const float*)d_in[5];
    const float* a1d   = (const float*)d_in[6];
    const float* b1    = (const float*)d_in[7];
    const float* W2    = (const float*)d_in[8];
    const float* a2s   = (const float*)d_in[9];
    const float* a2d   = (const float*)d_in[10];
    const float* b2    = (const float*)d_in[11];
    float* out = (float*)d_out;

    float *p_h1, *p_h2;
    int* p_cnt;
    __nv_bfloat16 *pW1h, *pW1l, *pW2h, *pW2l, *p_xh, *p_xl, *p_h1gh, *p_h1gl;
    cudaGetSymbolAddress((void**)&p_h1,   g_h1);
    cudaGetSymbolAddress((void**)&p_h2,   g_h2);
    cudaGetSymbolAddress((void**)&p_cnt,  g_cnt);
    cudaGetSymbolAddress((void**)&pW1h,   gW1h);
    cudaGetSymbolAddress((void**)&pW1l,   gW1l);
    cudaGetSymbolAddress((void**)&pW2h,   gW2h);
    cudaGetSymbolAddress((void**)&pW2l,   gW2l);
    cudaGetSymbolAddress((void**)&p_xh,   g_xh);
    cudaGetSymbolAddress((void**)&p_xl,   g_xl);
    cudaGetSymbolAddress((void**)&p_h1gh, g_h1gh);
    cudaGetSymbolAddress((void**)&p_h1gl, g_h1gl);

    const int STRB = 272;
    const int smem1 = 2 * 64 * STRB + 2 * 128 * STRB;   // 104448 (MT=64, NT=128)
    const int smem2 = 2 * 128 * STRB + 2 * 64 * STRB;   // 104448 (MT=128, NT=64)
    cudaFuncSetAttribute((const void*)k_gemm_mma<HC1, 64>,
                         cudaFuncAttributeMaxDynamicSharedMemorySize, smem1);
    cudaFuncSetAttribute((const void*)k_gemm_mma<HC2, 128>,
                         cudaFuncAttributeMaxDynamicSharedMemorySize, smem2);

    // --- prep (x split + weight transpose/split) ---
    const int NPREP = NN * DD + TT * HC1 * DD + TT * HC2 * HC1;
    k_prep<<<(NPREP + 255) / 256, 256>>>(x, W1, W2);

    // --- (type,dst) CSR build ---
    cudaMemsetAsync(p_cnt, 0, NSEG * sizeof(int));
    k_count<<<(EE + 255) / 256, 256>>>(edst, etype);
    k_scan_block<<<NB2, 1024>>>();
    k_scan_aux<<<1, 256>>>();
    k_add_aux<<<NB2, 1024>>>();
    k_scatter<<<(EE + 255) / 256, 256>>>(esrc, edst, etype);

    const int gat_blocks = (NSEG * 32 + 255) / 256;
    const int sc_blocks  = (TT * NN * HH + 255) / 256;

    // layer 1 (all t): h1 = x @ W1[t]
    {
        dim3 grid((NN + 63) / 64, TT);
        k_gemm_mma<HC1, 64><<<grid, 256, smem1>>>(p_xh, p_xl, 0,
                                                  pW1h, pW1l, p_h1, NN);
    }
    k_scores<C1V><<<sc_blocks, 256>>>(p_h1, a1s, a1d);
    k_gat<C1V, true><<<gat_blocks, 256>>>(p_h1, b1, nullptr, 0, 0,
                                          p_h1gh, p_h1gl, 1);
    // layer 2 (all t): h2 = h1g @ W2[t]
    {
        dim3 grid((NN + 127) / 128, TT);
        k_gemm_mma<HC2, 128><<<grid, 256, smem2>>>(p_h1gh, p_h1gl, (size_t)NN * HC1,
                                                   pW2h, pW2l, p_h2, NN);
    }
    k_scores<C2V><<<sc_blocks, 256>>>(p_h2, a2s, a2d);
    k_gat<C2V, false><<<gat_blocks, 256>>>(p_h2, b2, out, OUTW, HC2,
                                           nullptr, nullptr, 0);
}

// round 13
// speedup vs baseline: 1.1231x; 1.1231x over previous
#include <cuda_runtime.h>
#include <cuda_bf16.h>
#include <cstdint>

#define NN   50000
#define EE   800000
#define TT   4
#define HH   8
#define C1V  16
#define C2V  8
#define DD   128
#define HC1  128          // H*C1
#define HC2  64           // H*C2
#define OUTW 256          // T*H*C2
#define LRELU 0.2f

#define NSEG (NN * TT)    // 200000 (type,node) segments
#define NB2  196          // ceil(NSEG/1024)
#define MTILES 391        // ceil(50000/128)

// ---------------- scratch (static device globals; no allocation) -------------
__device__ __align__(16) float g_h1 [TT * NN * HC1];       // GEMM1 out (all t)
__device__ __align__(16) float g_h2 [TT * NN * HC2];       // GEMM2 out (all t)
__device__ __align__(16) float g_ss [TT * NN * HH];
__device__ __align__(16) float g_sd [TT * NN * HH];
__device__ __align__(16) __nv_bfloat16 g_xh [NN * DD];
__device__ __align__(16) __nv_bfloat16 g_xl [NN * DD];
__device__ __align__(16) __nv_bfloat16 g_h1gh[TT * NN * HC1];
__device__ __align__(16) __nv_bfloat16 g_h1gl[TT * NN * HC1];
__device__ __align__(16) __nv_bfloat16 gW1h[TT * HC1 * DD];
__device__ __align__(16) __nv_bfloat16 gW1l[TT * HC1 * DD];
__device__ __align__(16) __nv_bfloat16 gW2h[TT * HC2 * HC1];
__device__ __align__(16) __nv_bfloat16 gW2l[TT * HC2 * HC1];
__device__ int g_cnt [NSEG];
__device__ int g_offs[NSEG];
__device__ int g_cur [NSEG];
__device__ int g_src [EE];     // source node ids, sorted by (type,dst)
__device__ int g_aux [256];

// ============================ helpers ========================================
__device__ __forceinline__ uint32_t smem_u32(const void* p) {
    uint32_t a;
    asm("{ .reg .u64 t; cvta.to.shared.u64 t, %1; cvt.u32.u64 %0, t; }"
        : "=r"(a) : "l"(p));
    return a;
}

#define LDMX4(r0, r1, r2, r3, addr) \
    asm volatile("ldmatrix.sync.aligned.m8n8.x4.shared.b16 {%0,%1,%2,%3}, [%4];" \
        : "=r"(r0), "=r"(r1), "=r"(r2), "=r"(r3) : "r"(addr))

__device__ __forceinline__ void mma_bf16(float& c0, float& c1, float& c2, float& c3,
                                         uint32_t a0, uint32_t a1, uint32_t a2, uint32_t a3,
                                         uint32_t b0, uint32_t b1) {
    asm volatile(
        "mma.sync.aligned.m16n8k16.row.col.f32.bf16.bf16.f32 "
        "{%0,%1,%2,%3}, {%4,%5,%6,%7}, {%8,%9}, {%0,%1,%2,%3};"
        : "+f"(c0), "+f"(c1), "+f"(c2), "+f"(c3)
        : "r"(a0), "r"(a1), "r"(a2), "r"(a3), "r"(b0), "r"(b1));
}

// ---------------- (type,dst) CSR construction --------------------------------
__global__ void k_count(const int* __restrict__ dst, const int* __restrict__ ety) {
    int e = blockIdx.x * blockDim.x + threadIdx.x;
    if (e < EE) atomicAdd(&g_cnt[ety[e] * NN + dst[e]], 1);
}

__global__ void k_scan_block() {
    __shared__ int sh[1024];
    int i = blockIdx.x * 1024 + threadIdx.x;
    int v = (i < NSEG) ? g_cnt[i] : 0;
    sh[threadIdx.x] = v;
    __syncthreads();
    for (int d = 1; d < 1024; d <<= 1) {
        int t = (threadIdx.x >= d) ? sh[threadIdx.x - d] : 0;
        __syncthreads();
        sh[threadIdx.x] += t;
        __syncthreads();
    }
    if (i < NSEG) g_offs[i] = sh[threadIdx.x] - v;   // exclusive
    if (threadIdx.x == 1023) g_aux[blockIdx.x] = sh[1023];
}

__global__ void k_scan_aux() {
    __shared__ int sh[256];
    int tid = threadIdx.x;
    int v = (tid < NB2) ? g_aux[tid] : 0;
    sh[tid] = v;
    __syncthreads();
    for (int d = 1; d < 256; d <<= 1) {
        int t = (tid >= d) ? sh[tid - d] : 0;
        __syncthreads();
        sh[tid] += t;
        __syncthreads();
    }
    if (tid < NB2) g_aux[tid] = sh[tid] - v;         // exclusive
}

__global__ void k_add_aux() {
    int i = blockIdx.x * 1024 + threadIdx.x;
    if (i < NSEG) {
        int v = g_offs[i] + g_aux[blockIdx.x];
        g_offs[i] = v;
        g_cur[i]  = v;
    }
}

__global__ void k_scatter(const int* __restrict__ srcl, const int* __restrict__ dst,
                          const int* __restrict__ ety) {
    int e = blockIdx.x * blockDim.x + threadIdx.x;
    if (e < EE) {
        int pos = atomicAdd(&g_cur[ety[e] * NN + dst[e]], 1);
        g_src[pos] = srcl[e];
    }
}

// ---------------- combined prep: x split + weight transpose/split -------------
__global__ void k_prep(const float* __restrict__ x,
                       const float* __restrict__ W1, const float* __restrict__ W2) {
    const int NX = NN * DD;          // 6,400,000
    const int N1 = TT * HC1 * DD;    // 65536
    const int N2 = TT * HC2 * HC1;   // 32768
    int i = blockIdx.x * blockDim.x + threadIdx.x;
    if (i < NX) {
        float v = x[i];
        __nv_bfloat16 h = __float2bfloat16(v);
        g_xh[i] = h;
        g_xl[i] = __float2bfloat16(v - __bfloat162float(h));
    } else if (i < NX + N1) {
        int j = i - NX;
        int t = j >> 14, r = j & 16383;
        int n = r >> 7, k = r & 127;
        float v = W1[(t << 14) + k * HC1 + n];
        __nv_bfloat16 h = __float2bfloat16(v);
        gW1h[j] = h;
        gW1l[j] = __float2bfloat16(v - __bfloat162float(h));
    } else if (i < NX + N1 + N2) {
        int j = i - NX - N1;
        int t = j >> 13, r = j & 8191;
        int n = r >> 7, k = r & 127;
        float v = W2[t * 8192 + k * HC2 + n];
        __nv_bfloat16 h = __float2bfloat16(v);
        gW2h[j] = h;
        gW2l[j] = __float2bfloat16(v - __bfloat162float(h));
    }
}

// ---------------- HMMA bf16-split GEMM + fused score epilogue ----------------
// MT=128 x NT tile, 256 threads (8 warps: 2x4), 3-term bf16 split, fp32 acc.
// Also computes s_src/s_dst per (node, head) from the accumulator fragments.
template <int NT>
__global__ void __launch_bounds__(256, 1)
k_gemm_mma(const __nv_bfloat16* __restrict__ Ah, const __nv_bfloat16* __restrict__ Al,
           size_t aTstride,
           const __nv_bfloat16* __restrict__ Bh, const __nv_bfloat16* __restrict__ Bl,
           float* __restrict__ Cout, int M,
           const float* __restrict__ a_s, const float* __restrict__ a_d,
           float* __restrict__ ssout, float* __restrict__ sdout) {
    constexpr int K    = 128;
    constexpr int MT   = 128;
    constexpr int STRB = 272;
    constexpr int ASZ  = MT * STRB;
    constexpr int BSZ  = NT * STRB;
    constexpr int NW   = NT / 4;              // cols per warp (32 or 16)
    constexpr int NF   = NW / 8;              // n8 frags per warp (4 or 2)
    constexpr int MF   = MT / 32;             // 4
    constexpr int CH   = NT / 8;              // per-head channels (16 or 8)
    constexpr int FPH  = NF / 2;              // frags per head (2 or 1)

    extern __shared__ __align__(16) char smem[];
    uint32_t sb = smem_u32(smem);
    const uint32_t As = sb;
    const uint32_t Bs = sb + 2 * ASZ;

    int tid = threadIdx.x, wid = tid >> 5, lane = tid & 31;
    int m0 = blockIdx.x * MT;
    int t = blockIdx.y;
    Ah += (size_t)t * aTstride;
    Al += (size_t)t * aTstride;
    Bh += (size_t)t * NT * K;
    Bl += (size_t)t * NT * K;
    Cout  += (size_t)t * NN * NT;
    ssout += (size_t)t * NN * HH;
    sdout += (size_t)t * NN * HH;
    a_s   += (size_t)t * NT;      // per-type attention vectors (H*C == NT)
    a_d   += (size_t)t * NT;

    {
        for (int idx = tid; idx < MT * 16; idx += 256) {
            int row = idx >> 4, c = idx & 15;
            int gm = m0 + row;
            uint4 vh = make_uint4(0, 0, 0, 0), vl = vh;
            if (gm < M) {
                vh = *(const uint4*)&Ah[(size_t)gm * K + c * 8];
                vl = *(const uint4*)&Al[(size_t)gm * K + c * 8];
            }
            char* ph = smem + row * STRB + c * 16;
            *(uint4*)ph = vh;
            *(uint4*)(ph + ASZ) = vl;
        }
        for (int idx = tid; idx < NT * 16; idx += 256) {
            int row = idx >> 4, c = idx & 15;
            uint4 vh = *(const uint4*)&Bh[(size_t)row * K + c * 8];
            uint4 vl = *(const uint4*)&Bl[(size_t)row * K + c * 8];
            char* ph = smem + 2 * ASZ + row * STRB + c * 16;
            *(uint4*)ph = vh;
            *(uint4*)(ph + BSZ) = vl;
        }
    }
    __syncthreads();

    int warpM = wid >> 2;        // 0..1
    int warpN = wid & 3;         // 0..3
    int lr = lane & 7, lg = lane >> 3;

    uint32_t aRow = warpM * 64 + lr + (lg & 1) * 8;
    uint32_t aCol = (lg >> 1) * 8;
    uint32_t bRow = warpN * NW + lr + (lg >> 1) * 8;
    uint32_t bCol = (lg & 1) * 8;

    float c[MF][NF][4];
#pragma unroll
    for (int mf = 0; mf < MF; mf++)
#pragma unroll
        for (int nf = 0; nf < NF; nf++)
#pragma unroll
            for (int j = 0; j < 4; j++) c[mf][nf][j] = 0.f;

#pragma unroll
    for (int p = 0; p < 3; p++) {
        uint32_t Abase = As + ((p == 2) ? ASZ : 0);
        uint32_t Bbase = Bs + ((p == 1) ? BSZ : 0);
#pragma unroll
        for (int ks = 0; ks < 8; ks++) {
            int k0 = ks * 16;
            uint32_t a[MF][4];
#pragma unroll
            for (int mf = 0; mf < MF; mf++) {
                uint32_t ad = Abase + (aRow + mf * 16) * STRB + (k0 + aCol) * 2;
                LDMX4(a[mf][0], a[mf][1], a[mf][2], a[mf][3], ad);
            }
            uint32_t b[NF][2];
#pragma unroll
            for (int nf2 = 0; nf2 < NF / 2; nf2++) {
                uint32_t bd = Bbase + (bRow + nf2 * 16) * STRB + (k0 + bCol) * 2;
                uint32_t r0, r1, r2, r3;
                LDMX4(r0, r1, r2, r3, bd);
                b[2 * nf2][0] = r0; b[2 * nf2][1] = r1;
                b[2 * nf2 + 1][0] = r2; b[2 * nf2 + 1][1] = r3;
            }
#pragma unroll
            for (int mf = 0; mf < MF; mf++)
#pragma unroll
                for (int nf = 0; nf < NF; nf++)
                    mma_bf16(c[mf][nf][0], c[mf][nf][1], c[mf][nf][2], c[mf][nf][3],
                             a[mf][0], a[mf][1], a[mf][2], a[mf][3],
                             b[nf][0], b[nf][1]);
        }
    }

    // ---- epilogue: write C ----
    int g = lane >> 2, tq = lane & 3;
#pragma unroll
    for (int mf = 0; mf < MF; mf++) {
        int m = m0 + warpM * 64 + mf * 16 + g;
#pragma unroll
        for (int nf = 0; nf < NF; nf++) {
            int n = warpN * NW + nf * 8 + tq * 2;
            if (m < M)
                *(float2*)&Cout[(size_t)m * NT + n] = make_float2(c[mf][nf][0], c[mf][nf][1]);
            if (m + 8 < M)
                *(float2*)&Cout[(size_t)(m + 8) * NT + n] = make_float2(c[mf][nf][2], c[mf][nf][3]);
        }
    }

    // ---- fused scores: per (row, head) dot with a_s / a_d --------------------
    // Warp covers heads {2*warpN, 2*warpN+1}; head h spans frags hw*FPH..+FPH-1.
#pragma unroll
    for (int mf = 0; mf < MF; mf++) {
#pragma unroll
        for (int hw = 0; hw < 2; hw++) {
            int h = 2 * warpN + hw;
            float s0 = 0.f, s1 = 0.f, d0 = 0.f, d1 = 0.f;
#pragma unroll
            for (int f = 0; f < FPH; f++) {
                int nf = hw * FPH + f;
                int cidx = h * CH + f * 8 + tq * 2;
                float w0 = a_s[cidx], w1 = a_s[cidx + 1];
                float v0 = a_d[cidx], v1 = a_d[cidx + 1];
                s0 += c[mf][nf][0] * w0 + c[mf][nf][1] * w1;
                s1 += c[mf][nf][2] * w0 + c[mf][nf][3] * w1;
                d0 += c[mf][nf][0] * v0 + c[mf][nf][1] * v1;
                d1 += c[mf][nf][2] * v0 + c[mf][nf][3] * v1;
            }
            s0 += __shfl_xor_sync(0xffffffffu, s0, 1);
            s0 += __shfl_xor_sync(0xffffffffu, s0, 2);
            s1 += __shfl_xor_sync(0xffffffffu, s1, 1);
            s1 += __shfl_xor_sync(0xffffffffu, s1, 2);
            d0 += __shfl_xor_sync(0xffffffffu, d0, 1);
            d0 += __shfl_xor_sync(0xffffffffu, d0, 2);
            d1 += __shfl_xor_sync(0xffffffffu, d1, 1);
            d1 += __shfl_xor_sync(0xffffffffu, d1, 2);
            if (tq == 0) {
                int m = m0 + warpM * 64 + mf * 16 + g;
                if (m < M) {
                    ssout[(size_t)m * HH + h] = s0;
                    sdout[(size_t)m * HH + h] = d0;
                }
                if (m + 8 < M) {
                    ssout[(size_t)(m + 8) * HH + h] = s1;
                    sdout[(size_t)(m + 8) * HH + h] = d1;
                }
            }
        }
    }
}

// ---------------- GAT: one warp per (type,node), online softmax (R7 form) ----
template <int C, bool BF16OUT>
__global__ void k_gat(const float* __restrict__ featbase,
                      const float* __restrict__ biasbase,
                      float* __restrict__ outbase, int ostride, int ocol_step,
                      __nv_bfloat16* __restrict__ outh,
                      __nv_bfloat16* __restrict__ outl, int dorelu) {
    constexpr int HC = 8 * C;
    constexpr int VW = C / 4;               // 4 for C=16, 2 for C=8
    int seg = (blockIdx.x * blockDim.x + threadIdx.x) >> 5;
    if (seg >= NSEG) return;
    int lane = threadIdx.x & 31;
    int t = seg / NN;
    int node = seg - t * NN;
    int start = g_offs[seg];
    int deg   = g_cnt[seg];

    const float* feat = featbase + (size_t)t * NN * HC;
    const float* ssp  = g_ss + (size_t)t * NN * 8;
    const float* sdp  = g_sd + (size_t)t * NN * 8;
    const float* bias = biasbase + t * HC;

    int hd = lane >> 2;
    int cbase = (lane & 3) * VW;
    float sd_h = sdp[node * 8 + hd];

    // self-loop seeds the online softmax state
    float m = ssp[node * 8 + hd] + sd_h;
    m = m > 0.f ? m : LRELU * m;
    float denom = 1.f;

    float acc[VW];
    {
        const float* fp = &feat[(size_t)node * HC + hd * C + cbase];
        if constexpr (VW == 4) {
            float4 hv = *(const float4*)fp;
            acc[0] = hv.x; acc[1] = hv.y; acc[2] = hv.z; acc[3] = hv.w;
        } else {
            float2 hv = *(const float2*)fp;
            acc[0] = hv.x; acc[1] = hv.y;
        }
    }

    for (int i = 0; i < deg; i++) {
        int s = g_src[start + i];
        float u = ssp[s * 8 + hd] + sd_h;
        u = u > 0.f ? u : LRELU * u;
        float pe;
        if (u > m) {
            float r = __expf(m - u);
            denom = denom * r + 1.f;
#pragma unroll
            for (int j = 0; j < VW; j++) acc[j] *= r;
            m = u;
            pe = 1.f;
        } else {
            pe = __expf(u - m);
            denom += pe;
        }
        const float* fp = &feat[(size_t)s * HC + hd * C + cbase];
        if constexpr (VW == 4) {
            float4 hv = *(const float4*)fp;
            acc[0] += pe * hv.x; acc[1] += pe * hv.y;
            acc[2] += pe * hv.z; acc[3] += pe * hv.w;
        } else {
            float2 hv = *(const float2*)fp;
            acc[0] += pe * hv.x; acc[1] += pe * hv.y;
        }
    }

    float inv = 1.f / denom;
    float o[VW];
#pragma unroll
    for (int j = 0; j < VW; j++) {
        float v = acc[j] * inv + bias[hd * C + cbase + j];
        if (dorelu) v = fmaxf(v, 0.f);
        o[j] = v;
    }
    if constexpr (BF16OUT) {
        size_t ob = ((size_t)t * NN + node) * HC + hd * C + cbase;
#pragma unroll
        for (int j = 0; j < VW; j += 2) {
            __nv_bfloat16 h0 = __float2bfloat16(o[j]);
            __nv_bfloat16 h1b = __float2bfloat16(o[j + 1]);
            __nv_bfloat162 hp; hp.x = h0; hp.y = h1b;
            __nv_bfloat162 lp;
            lp.x = __float2bfloat16(o[j] - __bfloat162float(h0));
            lp.y = __float2bfloat16(o[j + 1] - __bfloat162float(h1b));
            *(__nv_bfloat162*)&outh[ob + j] = hp;
            *(__nv_bfloat162*)&outl[ob + j] = lp;
        }
    } else {
        float* op = &outbase[(size_t)node * ostride + t * ocol_step + hd * C + cbase];
        if constexpr (VW == 4) {
            *(float4*)op = make_float4(o[0], o[1], o[2], o[3]);
        } else {
            *(float2*)op = make_float2(o[0], o[1]);
        }
    }
}

// ---------------- launch ------------------------------------------------------
extern "C" void kernel_launch(void* const* d_in, const int* in_sizes, int n_in,
                              void* d_out, int out_size) {
    const float* x     = (const float*)d_in[0];
    const int*   esrc  = (const int*)  d_in[1];
    const int*   edst  = (const int*)  d_in[2];
    const int*   etype = (const int*)  d_in[3];
    const float* W1    = (const float*)d_in[4];
    const float* a1s   = (const float*)d_in[5];
    const float* a1d   = (const float*)d_in[6];
    const float* b1    = (const float*)d_in[7];
    const float* W2    = (const float*)d_in[8];
    const float* a2s   = (const float*)d_in[9];
    const float* a2d   = (const float*)d_in[10];
    const float* b2    = (const float*)d_in[11];
    float* out = (float*)d_out;

    float *p_h1, *p_h2, *p_ss, *p_sd;
    int* p_cnt;
    __nv_bfloat16 *pW1h, *pW1l, *pW2h, *pW2l, *p_xh, *p_xl, *p_h1gh, *p_h1gl;
    cudaGetSymbolAddress((void**)&p_h1,   g_h1);
    cudaGetSymbolAddress((void**)&p_h2,   g_h2);
    cudaGetSymbolAddress((void**)&p_ss,   g_ss);
    cudaGetSymbolAddress((void**)&p_sd,   g_sd);
    cudaGetSymbolAddress((void**)&p_cnt,  g_cnt);
    cudaGetSymbolAddress((void**)&pW1h,   gW1h);
    cudaGetSymbolAddress((void**)&pW1l,   gW1l);
    cudaGetSymbolAddress((void**)&pW2h,   gW2h);
    cudaGetSymbolAddress((void**)&pW2l,   gW2l);
    cudaGetSymbolAddress((void**)&p_xh,   g_xh);
    cudaGetSymbolAddress((void**)&p_xl,   g_xl);
    cudaGetSymbolAddress((void**)&p_h1gh, g_h1gh);
    cudaGetSymbolAddress((void**)&p_h1gl, g_h1gl);

    const int STRB = 272;
    const int smem1 = 4 * 128 * STRB;                   // 139264 (MT=128, NT=128)
    const int smem2 = 2 * 128 * STRB + 2 * 64 * STRB;   // 104448 (MT=128, NT=64)
    cudaFuncSetAttribute((const void*)k_gemm_mma<HC1>,
                         cudaFuncAttributeMaxDynamicSharedMemorySize, smem1);
    cudaFuncSetAttribute((const void*)k_gemm_mma<HC2>,
                         cudaFuncAttributeMaxDynamicSharedMemorySize, smem2);

    // --- fork: CSR build on a side stream, GEMM pipeline on the main stream ---
    cudaStream_t sB;
    cudaStreamCreateWithFlags(&sB, cudaStreamNonBlocking);
    cudaEvent_t eFork, eJoin;
    cudaEventCreateWithFlags(&eFork, cudaEventDisableTiming);
    cudaEventCreateWithFlags(&eJoin, cudaEventDisableTiming);

    cudaEventRecord(eFork, 0);
    cudaStreamWaitEvent(sB, eFork, 0);

    // CSR chain on side stream
    cudaMemsetAsync(p_cnt, 0, NSEG * sizeof(int), sB);
    k_count<<<(EE + 255) / 256, 256, 0, sB>>>(edst, etype);
    k_scan_block<<<NB2, 1024, 0, sB>>>();
    k_scan_aux<<<1, 256, 0, sB>>>();
    k_add_aux<<<NB2, 1024, 0, sB>>>();
    k_scatter<<<(EE + 255) / 256, 256, 0, sB>>>(esrc, edst, etype);
    cudaEventRecord(eJoin, sB);

    // main stream: prep + GEMM1 (+fused scores)
    const int NPREP = NN * DD + TT * HC1 * DD + TT * HC2 * HC1;
    k_prep<<<(NPREP + 255) / 256, 256>>>(x, W1, W2);
    {
        dim3 grid(MTILES, TT);
        k_gemm_mma<HC1><<<grid, 256, smem1>>>(p_xh, p_xl, 0,
                                              pW1h, pW1l, p_h1, NN,
                                              a1s, a1d, p_ss, p_sd);
    }

    // join: GAT1 needs both CSR and GEMM1
    cudaStreamWaitEvent(0, eJoin, 0);

    const int gat_blocks = (NSEG * 32 + 255) / 256;
    k_gat<C1V, true><<<gat_blocks, 256>>>(p_h1, b1, nullptr, 0, 0,
                                          p_h1gh, p_h1gl, 1);
    {
        dim3 grid(MTILES, TT);
        k_gemm_mma<HC2><<<grid, 256, smem2>>>(p_h1gh, p_h1gl, (size_t)NN * HC1,
                                              pW2h, pW2l, p_h2, NN,
                                              a2s, a2d, p_ss, p_sd);
    }
    k_gat<C2V, false><<<gat_blocks, 256>>>(p_h2, b2, out, OUTW, HC2,
                                           nullptr, nullptr, 0);

    cudaStreamDestroy(sB);
    cudaEventDestroy(eFork);
    cudaEventDestroy(eJoin);
}